// round 1
// baseline (speedup 1.0000x reference)
#include <cuda_runtime.h>

#define B_DIM 256
#define T_DIM 64
#define D_DIM 2048
#define THRESHOLD 0.99f
#define EPSILON 0.01f

// ---------------------------------------------------------------------------
// Kernel 1: per-batch ACT halting weight computation.
// grid = B, block = T (64 threads). Tiny; runtime negligible vs kernel 2.
// Writes weights -> out_weights[b*T+t], ponder_cost -> out_ponder[b].
// ---------------------------------------------------------------------------
__global__ void act_weights_kernel(const float* __restrict__ halt_probs,   // [B,T]
                                   const float* __restrict__ step_weights, // [B,T]
                                   float* __restrict__ out_weights,        // [B,T]
                                   float* __restrict__ out_ponder)         // [B]
{
    const int b = blockIdx.x;
    const int t = threadIdx.x;

    __shared__ float sp[T_DIM];
    __shared__ float s_red[T_DIM];
    __shared__ int   s_h;
    __shared__ float s_rem;

    sp[t] = halt_probs[b * T_DIM + t];
    __syncthreads();

    if (t == 0) {
        float cum = 0.0f;
        int   h   = T_DIM - 1;
        bool  found = false;
        for (int i = 0; i < T_DIM; i++) {
            cum += sp[i];
            if (!found && cum >= THRESHOLD) { found = true; h = i; }
        }
        // cumsum at halt step
        float cum_at = 0.0f;
        for (int i = 0; i <= h; i++) cum_at += sp[i];
        s_h   = h;
        s_rem = 1.0f - cum_at + sp[h];
    }
    __syncthreads();

    const int   h   = s_h;
    const float rem = s_rem;

    float w = (t < h) ? sp[t] : ((t == h) ? rem : 0.0f);
    w *= step_weights[b * T_DIM + t];

    // block reduce (64 threads) for weight sum
    s_red[t] = w;
    __syncthreads();
    #pragma unroll
    for (int off = T_DIM / 2; off > 0; off >>= 1) {
        if (t < off) s_red[t] += s_red[t + off];
        __syncthreads();
    }
    float wsum = s_red[0];
    wsum = fmaxf(wsum, EPSILON);
    __syncthreads();

    w = w / wsum;
    out_weights[b * T_DIM + t] = w;

    // ponder cost = sum_t w[t] * (t+1)
    s_red[t] = w * (float)(t + 1);
    __syncthreads();
    #pragma unroll
    for (int off = T_DIM / 2; off > 0; off >>= 1) {
        if (t < off) s_red[t] += s_red[t + off];
        __syncthreads();
    }
    if (t == 0) out_ponder[b] = s_red[0];
}

// ---------------------------------------------------------------------------
// Kernel 2: final_output[b,d] = sum_t weights[b,t] * outputs[b,t,d]
// HBM-bound: reads 128 MB. float4 vectorized; 2 blocks per batch,
// 256 threads each -> each thread owns one float4 column slice, loops T=64.
// ---------------------------------------------------------------------------
#define RBLK_THREADS 256
#define D4 (D_DIM / 4)                 // 512 float4 per row
#define BLOCKS_PER_B (D4 / RBLK_THREADS) // 2

__global__ void act_reduce_kernel(const float* __restrict__ outputs,  // [B,T,D]
                                  const float* __restrict__ weights,  // [B,T]
                                  float* __restrict__ final_out)      // [B,D]
{
    const int b      = blockIdx.x / BLOCKS_PER_B;
    const int chunk  = blockIdx.x % BLOCKS_PER_B;
    const int d4     = chunk * RBLK_THREADS + threadIdx.x; // float4 index in [0, D4)

    __shared__ float wsh[T_DIM];
    if (threadIdx.x < T_DIM) wsh[threadIdx.x] = weights[b * T_DIM + threadIdx.x];
    __syncthreads();

    const float4* base = reinterpret_cast<const float4*>(outputs)
                         + (size_t)b * T_DIM * D4 + d4;

    float4 acc = make_float4(0.f, 0.f, 0.f, 0.f);
    #pragma unroll 8
    for (int t = 0; t < T_DIM; t++) {
        const float  w = wsh[t];
        const float4 v = base[(size_t)t * D4];
        acc.x = fmaf(w, v.x, acc.x);
        acc.y = fmaf(w, v.y, acc.y);
        acc.z = fmaf(w, v.z, acc.z);
        acc.w = fmaf(w, v.w, acc.w);
    }

    reinterpret_cast<float4*>(final_out)[(size_t)b * D4 + d4] = acc;
}

// ---------------------------------------------------------------------------
// kernel_launch
// Inputs (metadata order): halt_probs [B,T,1], outputs [B,T,D], step_weights [B,T]
// Output: concat(final_output [B*D], ponder_cost [B], weights [B*T]) fp32
// ---------------------------------------------------------------------------
extern "C" void kernel_launch(void* const* d_in, const int* in_sizes, int n_in,
                              void* d_out, int out_size)
{
    const float* halt_probs   = (const float*)d_in[0];
    const float* outputs      = (const float*)d_in[1];
    const float* step_weights = (const float*)d_in[2];

    float* out         = (float*)d_out;
    float* final_out   = out;                              // [B,D]
    float* ponder_out  = out + (size_t)B_DIM * D_DIM;      // [B]
    float* weights_out = ponder_out + B_DIM;               // [B,T]

    act_weights_kernel<<<B_DIM, T_DIM>>>(halt_probs, step_weights,
                                         weights_out, ponder_out);

    act_reduce_kernel<<<B_DIM * BLOCKS_PER_B, RBLK_THREADS>>>(outputs,
                                                              weights_out,
                                                              final_out);
}

// round 2
// speedup vs baseline: 1.1415x; 1.1415x over previous
#include <cuda_runtime.h>

#define B_DIM 256
#define T_DIM 64
#define D_DIM 2048
#define THRESHOLD 0.99f
#define EPSILON 0.01f

#define THREADS 128
#define D4 (D_DIM / 4)                    // 512 float4 per row
#define BLOCKS_PER_B (D4 / THREADS)       // 4
#define TBATCH 8

// ---------------------------------------------------------------------------
// Fused kernel: each block (b, chunk) recomputes the halting weights for its
// batch (cheap: T=64), then does the HBM-bound weighted reduction over its
// 128 float4 columns. chunk==0 blocks also write weights + ponder_cost.
// grid = B * 4, block = 128.
// ---------------------------------------------------------------------------
__global__ __launch_bounds__(THREADS)
void act_fused_kernel(const float* __restrict__ halt_probs,   // [B,T]
                      const float* __restrict__ outputs,      // [B,T,D]
                      const float* __restrict__ step_weights, // [B,T]
                      float* __restrict__ final_out,          // [B,D]
                      float* __restrict__ out_ponder,         // [B]
                      float* __restrict__ out_weights)        // [B,T]
{
    const int b     = blockIdx.x / BLOCKS_PER_B;
    const int chunk = blockIdx.x % BLOCKS_PER_B;
    const int tid   = threadIdx.x;

    __shared__ float sp[T_DIM];    // halt_p
    __shared__ float wsh[T_DIM];   // final normalized weights
    __shared__ int   s_h;
    __shared__ float s_rem;
    __shared__ float s_wsum;

    // ---- prologue: halting weights for batch b ----
    if (tid < T_DIM) sp[tid] = halt_probs[b * T_DIM + tid];
    __syncthreads();

    if (tid == 0) {
        float cum = 0.0f;
        int   h   = T_DIM - 1;
        bool  found = false;
        #pragma unroll
        for (int i = 0; i < T_DIM; i++) {
            cum += sp[i];
            if (!found && cum >= THRESHOLD) { found = true; h = i; }
        }
        float cum_at = 0.0f;
        for (int i = 0; i <= h; i++) cum_at += sp[i];
        s_h   = h;
        s_rem = 1.0f - cum_at + sp[h];
    }
    __syncthreads();

    const int   h   = s_h;
    const float rem = s_rem;

    if (tid < T_DIM) {
        float w = (tid < h) ? sp[tid] : ((tid == h) ? rem : 0.0f);
        w *= step_weights[b * T_DIM + tid];
        wsh[tid] = w;
    }
    __syncthreads();

    if (tid == 0) {
        float s = 0.0f;
        #pragma unroll
        for (int i = 0; i < T_DIM; i++) s += wsh[i];
        s_wsum = fmaxf(s, EPSILON);
    }
    __syncthreads();

    const float inv_wsum = 1.0f / s_wsum;
    if (tid < T_DIM) wsh[tid] *= inv_wsum;
    __syncthreads();

    if (chunk == 0) {
        if (tid < T_DIM) out_weights[b * T_DIM + tid] = wsh[tid];
        if (tid == 0) {
            float pc = 0.0f;
            #pragma unroll
            for (int i = 0; i < T_DIM; i++) pc += wsh[i] * (float)(i + 1);
            out_ponder[b] = pc;
        }
    }

    // ---- main loop: weighted reduction over T, batched loads for MLP ----
    const int d4 = chunk * THREADS + tid;   // float4 column in [0, D4)
    const float4* __restrict__ base =
        reinterpret_cast<const float4*>(outputs) + (size_t)b * T_DIM * D4 + d4;

    float4 acc = make_float4(0.f, 0.f, 0.f, 0.f);

    #pragma unroll 1
    for (int t0 = 0; t0 < T_DIM; t0 += TBATCH) {
        float4 v[TBATCH];
        #pragma unroll
        for (int i = 0; i < TBATCH; i++)
            v[i] = base[(size_t)(t0 + i) * D4];
        #pragma unroll
        for (int i = 0; i < TBATCH; i++) {
            const float w = wsh[t0 + i];
            acc.x = fmaf(w, v[i].x, acc.x);
            acc.y = fmaf(w, v[i].y, acc.y);
            acc.z = fmaf(w, v[i].z, acc.z);
            acc.w = fmaf(w, v[i].w, acc.w);
        }
    }

    reinterpret_cast<float4*>(final_out)[(size_t)b * D4 + d4] = acc;
}

// ---------------------------------------------------------------------------
// kernel_launch
// Inputs: halt_probs [B,T,1], outputs [B,T,D], step_weights [B,T]  (fp32)
// Output: concat(final_output [B*D], ponder_cost [B], weights [B*T]) fp32
// ---------------------------------------------------------------------------
extern "C" void kernel_launch(void* const* d_in, const int* in_sizes, int n_in,
                              void* d_out, int out_size)
{
    const float* halt_probs   = (const float*)d_in[0];
    const float* outputs      = (const float*)d_in[1];
    const float* step_weights = (const float*)d_in[2];

    float* out         = (float*)d_out;
    float* final_out   = out;                              // [B,D]
    float* ponder_out  = out + (size_t)B_DIM * D_DIM;      // [B]
    float* weights_out = ponder_out + B_DIM;               // [B,T]

    act_fused_kernel<<<B_DIM * BLOCKS_PER_B, THREADS>>>(
        halt_probs, outputs, step_weights,
        final_out, ponder_out, weights_out);
}